// round 2
// baseline (speedup 1.0000x reference)
#include <cuda_runtime.h>

#define PN 100000
#define LLEN 5
#define NLK 10000
#define DD 32
#define TT 8
#define RUN 256

// Scratch (no allocations allowed)
__device__ float g_path_state[PN * DD];        // 12.8 MB
__device__ float g_link_state[NLK * DD];       // 1.28 MB
__device__ float g_lg[NLK * 3 * DD];           // 3.84 MB : link_state @ Wp + bp[0]
__device__ float g_m[NLK * DD];                // 1.28 MB : per-link message accumulator

__device__ __forceinline__ float fexp2(float x) {
    float r; asm("ex2.approx.f32 %0, %1;" : "=f"(r) : "f"(x)); return r;
}
__device__ __forceinline__ float frcp(float x) {
    float r; asm("rcp.approx.f32 %0, %1;" : "=f"(r) : "f"(x)); return r;
}
__device__ __forceinline__ float fsig(float x) {
    // 1/(1+exp(-x)); ex2/rcp approx ~1 ulp — far below 1e-3 gate
    return frcp(1.0f + fexp2(-1.4426950408889634f * x));
}
__device__ __forceinline__ float ftanhf_(float x) {
    // tanh(x) = 2/(1+exp(-2x)) - 1 ; avoids tanh.approx's ~5e-4 abs error
    float e = fexp2(-2.8853900817779268f * x);
    return fmaf(2.0f, frcp(1.0f + e), -1.0f);
}
__device__ __forceinline__ float fselu(float x) {
    const float sc = 1.0507009873554805f;
    const float sa = 1.7580993408473768f;  // scale*alpha
    float neg = sa * (fexp2(1.4426950408889634f * x) - 1.0f);
    return x > 0.0f ? sc * x : neg;
}

// ---------------------------------------------------------------------------
// Init path_state[P,32]: {bandwith, tos, packets, AvgPkS, 0...}
__global__ void init_path_kernel(const float* __restrict__ bw, const float* __restrict__ tos,
                                 const float* __restrict__ pk, const float* __restrict__ avg) {
    int i = blockIdx.x * blockDim.x + threadIdx.x;
    if (i >= PN * DD) return;
    int p = i >> 5, c = i & 31;
    float v = 0.0f;
    if (c == 0) v = bw[p];
    else if (c == 1) v = tos[p];
    else if (c == 2) v = pk[p];
    else if (c == 3) v = avg[p];
    g_path_state[i] = v;
}

// Init link_state[NL,32] = {cap, pol, wt, 0...}; zero m; lg = link_state@Wp + bp0
// (only first 3 rows of Wp contribute initially)
__global__ void init_link_kernel(const float* __restrict__ cap, const float* __restrict__ pol,
                                 const float* __restrict__ wt,
                                 const float* __restrict__ Wp, const float* __restrict__ bp) {
    int w = (blockIdx.x * blockDim.x + threadIdx.x) >> 5;
    int lane = threadIdx.x & 31;
    if (w >= NLK) return;
    float c0 = __ldg(&cap[w]), c1 = __ldg(&pol[w]), c2 = __ldg(&wt[w]);
    float v = (lane == 0) ? c0 : (lane == 1) ? c1 : (lane == 2) ? c2 : 0.0f;
    g_link_state[w * DD + lane] = v;
    g_m[w * DD + lane] = 0.0f;
#pragma unroll
    for (int g = 0; g < 3; g++) {
        int c = g * 32 + lane;
        float o = __ldg(&bp[c]);
        o = fmaf(c0, __ldg(&Wp[c]),       o);
        o = fmaf(c1, __ldg(&Wp[96 + c]),  o);
        o = fmaf(c2, __ldg(&Wp[192 + c]), o);
        g_lg[w * 96 + c] = o;
    }
}

// ---------------------------------------------------------------------------
// Path phase: warp per path, 5 GRU steps. Lane c owns gate columns c/c+32/c+64.
// Up weights live in registers (96/lane), h broadcast via shfl.
// After each step, h is RED-added into m[link] (coalesced, one line per warp).
__global__ void __launch_bounds__(256, 2)
path_kernel(const int* __restrict__ links, const float* __restrict__ Up,
            const float* __restrict__ bp) {
    int w = (blockIdx.x * blockDim.x + threadIdx.x) >> 5;
    int lane = threadIdx.x & 31;
    if (w >= PN) return;

    float uz[32], ur[32], un[32];
#pragma unroll
    for (int l = 0; l < 32; l++) {
        uz[l] = __ldg(&Up[l * 96 + lane]);
        ur[l] = __ldg(&Up[l * 96 + 32 + lane]);
        un[l] = __ldg(&Up[l * 96 + 64 + lane]);
    }
    float b1z = __ldg(&bp[96 + lane]);
    float b1r = __ldg(&bp[128 + lane]);
    float b1n = __ldg(&bp[160 + lane]);

    float h = g_path_state[w * DD + lane];

    int lka[LLEN];
#pragma unroll
    for (int s = 0; s < LLEN; s++) lka[s] = __ldg(&links[w * LLEN + s]);

#pragma unroll
    for (int s = 0; s < LLEN; s++) {
        const float* lp = &g_lg[(size_t)lka[s] * 96];
        float xz = __ldg(&lp[lane]);
        float xr = __ldg(&lp[32 + lane]);
        float xn = __ldg(&lp[64 + lane]);
        float az = b1z, ar = b1r, an = b1n;
#pragma unroll
        for (int l = 0; l < 32; l++) {
            float hl = __shfl_sync(0xffffffffu, h, l);
            az = fmaf(hl, uz[l], az);
            ar = fmaf(hl, ur[l], ar);
            an = fmaf(hl, un[l], an);
        }
        float z = fsig(xz + az);
        float r = fsig(xr + ar);
        float n = ftanhf_(fmaf(r, an, xn));
        h = fmaf(z, h - n, n);             // z*h + (1-z)*n
        atomicAdd(&g_m[lka[s] * DD + lane], h);
    }
    g_path_state[w * DD + lane] = h;
}

// ---------------------------------------------------------------------------
// Link phase: warp per link. GRU(m, link_state), then refresh lg, re-zero m.
__global__ void __launch_bounds__(256)
link_kernel(const float* __restrict__ Wl, const float* __restrict__ Ul,
            const float* __restrict__ bl,
            const float* __restrict__ Wp, const float* __restrict__ bp) {
    int w = (blockIdx.x * blockDim.x + threadIdx.x) >> 5;
    int lane = threadIdx.x & 31;
    if (w >= NLK) return;

    float x = g_m[w * DD + lane];
    float h = g_link_state[w * DD + lane];

    float az = __ldg(&bl[lane]),       ar = __ldg(&bl[32 + lane]),  an = __ldg(&bl[64 + lane]);
    float hz = __ldg(&bl[96 + lane]),  hr = __ldg(&bl[128 + lane]), hn = __ldg(&bl[160 + lane]);
#pragma unroll
    for (int l = 0; l < 32; l++) {
        float xl = __shfl_sync(0xffffffffu, x, l);
        float hl = __shfl_sync(0xffffffffu, h, l);
        az = fmaf(xl, __ldg(&Wl[l * 96 + lane]),      az);
        ar = fmaf(xl, __ldg(&Wl[l * 96 + 32 + lane]), ar);
        an = fmaf(xl, __ldg(&Wl[l * 96 + 64 + lane]), an);
        hz = fmaf(hl, __ldg(&Ul[l * 96 + lane]),      hz);
        hr = fmaf(hl, __ldg(&Ul[l * 96 + 32 + lane]), hr);
        hn = fmaf(hl, __ldg(&Ul[l * 96 + 64 + lane]), hn);
    }
    float z = fsig(az + hz);
    float r = fsig(ar + hr);
    float n = ftanhf_(fmaf(r, hn, an));
    float h2 = fmaf(z, h - n, n);
    g_link_state[w * DD + lane] = h2;
    g_m[w * DD + lane] = 0.0f;            // ready for next iteration

    // lg = h2 @ Wp + bp[0]
    float gz = __ldg(&bp[lane]), gr = __ldg(&bp[32 + lane]), gn = __ldg(&bp[64 + lane]);
#pragma unroll
    for (int l = 0; l < 32; l++) {
        float hl = __shfl_sync(0xffffffffu, h2, l);
        gz = fmaf(hl, __ldg(&Wp[l * 96 + lane]),      gz);
        gr = fmaf(hl, __ldg(&Wp[l * 96 + 32 + lane]), gr);
        gn = fmaf(hl, __ldg(&Wp[l * 96 + 64 + lane]), gn);
    }
    g_lg[w * 96 + lane]      = gz;
    g_lg[w * 96 + 32 + lane] = gr;
    g_lg[w * 96 + 64 + lane] = gn;
}

// ---------------------------------------------------------------------------
// Readout: warp handles 4 paths (amortizes weight loads 4x). Lane owns 8
// contiguous hidden units; float4 weight loads; shfl-broadcast activations.
__global__ void __launch_bounds__(256, 2)
readout_kernel(const float* __restrict__ R1, const float* __restrict__ Rb1,
               const float* __restrict__ R2, const float* __restrict__ Rb2,
               const float* __restrict__ R3, const float* __restrict__ Rb3,
               float* __restrict__ out) {
    int w = (blockIdx.x * blockDim.x + threadIdx.x) >> 5;
    int lane = threadIdx.x & 31;
    if (w >= PN / 4) return;
    int p0 = w * 4;
    int cb = lane * 8;

    float ps[4];
#pragma unroll
    for (int q = 0; q < 4; q++) ps[q] = g_path_state[(p0 + q) * DD + lane];

    float4 b1a = __ldg((const float4*)&Rb1[cb]);
    float4 b1b = __ldg((const float4*)&Rb1[cb + 4]);
    float h1[4][8];
#pragma unroll
    for (int q = 0; q < 4; q++) {
        h1[q][0] = b1a.x; h1[q][1] = b1a.y; h1[q][2] = b1a.z; h1[q][3] = b1a.w;
        h1[q][4] = b1b.x; h1[q][5] = b1b.y; h1[q][6] = b1b.z; h1[q][7] = b1b.w;
    }
    for (int l = 0; l < 32; l++) {
        float4 wa = __ldg((const float4*)&R1[l * RUN + cb]);
        float4 wb = __ldg((const float4*)&R1[l * RUN + cb + 4]);
        float wv[8] = {wa.x, wa.y, wa.z, wa.w, wb.x, wb.y, wb.z, wb.w};
#pragma unroll
        for (int q = 0; q < 4; q++) {
            float v = __shfl_sync(0xffffffffu, ps[q], l);
#pragma unroll
            for (int j = 0; j < 8; j++) h1[q][j] = fmaf(v, wv[j], h1[q][j]);
        }
    }
#pragma unroll
    for (int q = 0; q < 4; q++)
#pragma unroll
        for (int j = 0; j < 8; j++) h1[q][j] = fselu(h1[q][j]);

    float4 b2a = __ldg((const float4*)&Rb2[cb]);
    float4 b2b = __ldg((const float4*)&Rb2[cb + 4]);
    float h2[4][8];
#pragma unroll
    for (int q = 0; q < 4; q++) {
        h2[q][0] = b2a.x; h2[q][1] = b2a.y; h2[q][2] = b2a.z; h2[q][3] = b2a.w;
        h2[q][4] = b2b.x; h2[q][5] = b2b.y; h2[q][6] = b2b.z; h2[q][7] = b2b.w;
    }
#pragma unroll
    for (int reg = 0; reg < 8; reg++) {
        for (int owner = 0; owner < 32; owner++) {
            int jj = owner * 8 + reg;
            float4 wa = __ldg((const float4*)&R2[jj * RUN + cb]);
            float4 wb = __ldg((const float4*)&R2[jj * RUN + cb + 4]);
            float wv[8] = {wa.x, wa.y, wa.z, wa.w, wb.x, wb.y, wb.z, wb.w};
#pragma unroll
            for (int q = 0; q < 4; q++) {
                float v = __shfl_sync(0xffffffffu, h1[q][reg], owner);
#pragma unroll
                for (int j = 0; j < 8; j++) h2[q][j] = fmaf(v, wv[j], h2[q][j]);
            }
        }
    }
#pragma unroll
    for (int q = 0; q < 4; q++)
#pragma unroll
        for (int j = 0; j < 8; j++) h2[q][j] = fselu(h2[q][j]);

    float4 r3a = __ldg((const float4*)&R3[cb]);
    float4 r3b = __ldg((const float4*)&R3[cb + 4]);
    float rv[8] = {r3a.x, r3a.y, r3a.z, r3a.w, r3b.x, r3b.y, r3b.z, r3b.w};
    float b3 = __ldg(&Rb3[0]);
#pragma unroll
    for (int q = 0; q < 4; q++) {
        float o = 0.0f;
#pragma unroll
        for (int j = 0; j < 8; j++) o = fmaf(h2[q][j], rv[j], o);
#pragma unroll
        for (int off = 16; off > 0; off >>= 1) o += __shfl_xor_sync(0xffffffffu, o, off);
        if (lane == 0) out[p0 + q] = o + b3;
    }
}

// ---------------------------------------------------------------------------
extern "C" void kernel_launch(void* const* d_in, const int* in_sizes, int n_in,
                              void* d_out, int out_size) {
    const int*   links = (const int*)d_in[0];
    // d_in[1]=paths, d_in[2]=seqs : structure is regular (repeat/tile) — unused
    const float* cap = (const float*)d_in[3];
    const float* pol = (const float*)d_in[4];
    const float* wt  = (const float*)d_in[5];
    const float* bw  = (const float*)d_in[6];
    const float* tos = (const float*)d_in[7];
    const float* pk  = (const float*)d_in[8];
    const float* avg = (const float*)d_in[9];
    const float* Wp  = (const float*)d_in[10];
    const float* Up  = (const float*)d_in[11];
    const float* bp  = (const float*)d_in[12];
    const float* Wl  = (const float*)d_in[13];
    const float* Ul  = (const float*)d_in[14];
    const float* bl  = (const float*)d_in[15];
    const float* R1  = (const float*)d_in[16];
    const float* Rb1 = (const float*)d_in[17];
    const float* R2  = (const float*)d_in[18];
    const float* Rb2 = (const float*)d_in[19];
    const float* R3  = (const float*)d_in[20];
    const float* Rb3 = (const float*)d_in[21];
    float* out = (float*)d_out;

    init_path_kernel<<<(PN * DD + 255) / 256, 256>>>(bw, tos, pk, avg);
    init_link_kernel<<<(NLK * 32 + 255) / 256, 256>>>(cap, pol, wt, Wp, bp);

    for (int t = 0; t < TT; t++) {
        path_kernel<<<(PN * 32 + 255) / 256, 256>>>(links, Up, bp);
        if (t < TT - 1)  // final link update is dead (readout uses path_state only)
            link_kernel<<<(NLK * 32 + 255) / 256, 256>>>(Wl, Ul, bl, Wp, bp);
    }

    readout_kernel<<<((PN / 4) * 32 + 255) / 256, 256>>>(R1, Rb1, R2, Rb2, R3, Rb3, out);
}

// round 4
// speedup vs baseline: 1.2733x; 1.2733x over previous
#include <cuda_runtime.h>
#include <cstdint>

#define PN 100000
#define LLEN 5
#define NLK 10000
#define DD 32
#define TT 8
#define RUN 256

// Scratch (no allocations allowed)
__device__ float g_path_state[PN * DD];        // 12.8 MB
__device__ float g_link_state[NLK * DD];       // 1.28 MB
__device__ float g_lg[NLK * 3 * DD];           // 3.84 MB : link_state @ Wp + bp[0]
__device__ float g_m[NLK * DD];                // 1.28 MB : per-link message accumulator

__device__ __forceinline__ float fexp2(float x) {
    float r; asm("ex2.approx.f32 %0, %1;" : "=f"(r) : "f"(x)); return r;
}
__device__ __forceinline__ float frcp(float x) {
    float r; asm("rcp.approx.f32 %0, %1;" : "=f"(r) : "f"(x)); return r;
}
__device__ __forceinline__ float fsig(float x) {
    return frcp(1.0f + fexp2(-1.4426950408889634f * x));
}
__device__ __forceinline__ float ftanhf_(float x) {
    float e = fexp2(-2.8853900817779268f * x);
    return fmaf(2.0f, frcp(1.0f + e), -1.0f);
}
__device__ __forceinline__ float fselu(float x) {
    const float sc = 1.0507009873554805f;
    const float sa = 1.7580993408473768f;
    float neg = sa * (fexp2(1.4426950408889634f * x) - 1.0f);
    return x > 0.0f ? sc * x : neg;
}
__device__ __forceinline__ unsigned cvt_tf32(float f) {
    unsigned u; asm("cvt.rna.tf32.f32 %0, %1;" : "=r"(u) : "f"(f)); return u;
}
__device__ __forceinline__ void mma_tf32(float d[4], const unsigned a[4], const unsigned b0,
                                         const unsigned b1) {
    asm volatile(
        "mma.sync.aligned.m16n8k8.row.col.f32.tf32.tf32.f32 "
        "{%0,%1,%2,%3},{%4,%5,%6,%7},{%8,%9},{%0,%1,%2,%3};"
        : "+f"(d[0]), "+f"(d[1]), "+f"(d[2]), "+f"(d[3])
        : "r"(a[0]), "r"(a[1]), "r"(a[2]), "r"(a[3]), "r"(b0), "r"(b1));
}

// ---------------------------------------------------------------------------
__global__ void init_path_kernel(const float* __restrict__ bw, const float* __restrict__ tos,
                                 const float* __restrict__ pk, const float* __restrict__ avg) {
    int i = blockIdx.x * blockDim.x + threadIdx.x;
    if (i >= PN * DD) return;
    int p = i >> 5, c = i & 31;
    float v = 0.0f;
    if (c == 0) v = bw[p];
    else if (c == 1) v = tos[p];
    else if (c == 2) v = pk[p];
    else if (c == 3) v = avg[p];
    g_path_state[i] = v;
}

__global__ void init_link_kernel(const float* __restrict__ cap, const float* __restrict__ pol,
                                 const float* __restrict__ wt,
                                 const float* __restrict__ Wp, const float* __restrict__ bp) {
    int w = (blockIdx.x * blockDim.x + threadIdx.x) >> 5;
    int lane = threadIdx.x & 31;
    if (w >= NLK) return;
    float c0 = __ldg(&cap[w]), c1 = __ldg(&pol[w]), c2 = __ldg(&wt[w]);
    float v = (lane == 0) ? c0 : (lane == 1) ? c1 : (lane == 2) ? c2 : 0.0f;
    g_link_state[w * DD + lane] = v;
    g_m[w * DD + lane] = 0.0f;
#pragma unroll
    for (int g = 0; g < 3; g++) {
        int c = g * 32 + lane;
        float o = __ldg(&bp[c]);
        o = fmaf(c0, __ldg(&Wp[c]),       o);
        o = fmaf(c1, __ldg(&Wp[96 + c]),  o);
        o = fmaf(c2, __ldg(&Wp[192 + c]), o);
        g_lg[w * 96 + c] = o;
    }
}

// ---------------------------------------------------------------------------
// Path phase via tensor cores with 3xTF32 error compensation (fp32-equivalent).
// One warp handles 16 paths. Recurrent GEMM H[16,32]@Up[32,96] as 12 n-tiles x
// 4 k-tiles of mma.m16n8k8, each computed as hi*hi + lo*hi + hi*lo.
// B fragments (hi,lo pre-split) staged once per block in 24KB smem.
__global__ void __launch_bounds__(128)
path_mma_kernel(const int* __restrict__ links, const float* __restrict__ Up,
                const float* __restrict__ bp) {
    __shared__ uint4 sB[48 * 32];   // [(nt*4+kt)*32 + lane] = {hi0, hi1, lo0, lo1}

    int lane = threadIdx.x & 31;

    // Cooperative B-fragment staging (warp-uniform data, fragment order).
    for (int idx = threadIdx.x; idx < 48 * 32; idx += blockDim.x) {
        int li = idx & 31;
        int t = idx >> 5;           // nt*4 + kt
        int nt = t >> 2, kt = t & 3;
        int gi = li >> 2, mi = li & 3;
        float w0 = __ldg(&Up[(kt * 8 + mi)     * 96 + nt * 8 + gi]);
        float w1 = __ldg(&Up[(kt * 8 + mi + 4) * 96 + nt * 8 + gi]);
        unsigned h0 = cvt_tf32(w0), h1 = cvt_tf32(w1);
        unsigned l0 = cvt_tf32(w0 - __uint_as_float(h0));
        unsigned l1 = cvt_tf32(w1 - __uint_as_float(h1));
        sB[idx] = make_uint4(h0, h1, l0, l1);
    }
    __syncthreads();

    int wid = (blockIdx.x * blockDim.x + threadIdx.x) >> 5;
    int p0 = wid * 16;
    if (p0 >= PN) return;
    int g = lane >> 2, m = lane & 3;
    int pA = p0 + g, pB = p0 + g + 8;

    // h in D-layout: h[jt] covers cols {8jt+2m, +1}, rows {pA, pB}
    float h[4][4];
#pragma unroll
    for (int jt = 0; jt < 4; jt++) {
        float2 ha = *(const float2*)&g_path_state[pA * DD + 8 * jt + 2 * m];
        float2 hb = *(const float2*)&g_path_state[pB * DD + 8 * jt + 2 * m];
        h[jt][0] = ha.x; h[jt][1] = ha.y; h[jt][2] = hb.x; h[jt][3] = hb.y;
    }

    int src0 = (lane & ~3) | (m >> 1);      // owner lane of col m (within k8 tile)
    int src1 = src0 + 2;                    // owner lane of col m+4
    bool odd = (m & 1);

#pragma unroll 1
    for (int s = 0; s < LLEN; s++) {
        int lkA = __ldg(&links[pA * LLEN + s]);
        int lkB = __ldg(&links[pB * LLEN + s]);
        const float* lgA = g_lg + lkA * 96;
        const float* lgB = g_lg + lkB * 96;

        // A fragments from h (D-layout -> A-layout), split hi/lo for 3xTF32.
        unsigned ah[4][4], al[4][4];
#pragma unroll
        for (int kt = 0; kt < 4; kt++) {
            float v[4];
            float s00 = __shfl_sync(0xffffffffu, h[kt][0], src0);
            float s01 = __shfl_sync(0xffffffffu, h[kt][1], src0);
            v[0] = odd ? s01 : s00;
            float s10 = __shfl_sync(0xffffffffu, h[kt][2], src0);
            float s11 = __shfl_sync(0xffffffffu, h[kt][3], src0);
            v[1] = odd ? s11 : s10;
            float s20 = __shfl_sync(0xffffffffu, h[kt][0], src1);
            float s21 = __shfl_sync(0xffffffffu, h[kt][1], src1);
            v[2] = odd ? s21 : s20;
            float s30 = __shfl_sync(0xffffffffu, h[kt][2], src1);
            float s31 = __shfl_sync(0xffffffffu, h[kt][3], src1);
            v[3] = odd ? s31 : s30;
#pragma unroll
            for (int e = 0; e < 4; e++) {
                unsigned hi = cvt_tf32(v[e]);
                ah[kt][e] = hi;
                al[kt][e] = cvt_tf32(v[e] - __uint_as_float(hi));
            }
        }

        // D init: z,r tiles = x-gate + recurrent bias; n tiles = recurrent bias
        float d[12][4];
#pragma unroll
        for (int nt = 0; nt < 8; nt++) {
            int gate = nt >> 2, jt = nt & 3;
            int coff = gate * 32 + 8 * jt + 2 * m;
            float2 br = *(const float2*)&bp[96 + coff];
            float2 xA = *(const float2*)&lgA[coff];
            float2 xB = *(const float2*)&lgB[coff];
            d[nt][0] = xA.x + br.x; d[nt][1] = xA.y + br.y;
            d[nt][2] = xB.x + br.x; d[nt][3] = xB.y + br.y;
        }
#pragma unroll
        for (int nt = 8; nt < 12; nt++) {
            int jt = nt & 3;
            int coff = 64 + 8 * jt + 2 * m;
            float2 br = *(const float2*)&bp[96 + coff];
            d[nt][0] = br.x; d[nt][1] = br.y; d[nt][2] = br.x; d[nt][3] = br.y;
        }

        // GEMM: 12 n-tiles x 4 k-tiles x 3 compensated mma
#pragma unroll
        for (int nt = 0; nt < 12; nt++)
#pragma unroll
            for (int kt = 0; kt < 4; kt++) {
                uint4 b = sB[(nt * 4 + kt) * 32 + lane];
                mma_tf32(d[nt], ah[kt], b.x, b.y);   // hi * hi
                mma_tf32(d[nt], al[kt], b.x, b.y);   // lo * hi
                mma_tf32(d[nt], ah[kt], b.z, b.w);   // hi * lo
            }

        // Elementwise GRU + message scatter
#pragma unroll
        for (int jt = 0; jt < 4; jt++) {
            int coff = 64 + 8 * jt + 2 * m;
            float2 xnA = *(const float2*)&lgA[coff];
            float2 xnB = *(const float2*)&lgB[coff];
            float xn[4] = {xnA.x, xnA.y, xnB.x, xnB.y};
#pragma unroll
            for (int e = 0; e < 4; e++) {
                float z = fsig(d[jt][e]);
                float r = fsig(d[4 + jt][e]);
                float n = ftanhf_(fmaf(r, d[8 + jt][e], xn[e]));
                h[jt][e] = fmaf(z, h[jt][e] - n, n);
            }
            int cA = 8 * jt + 2 * m;
            atomicAdd(&g_m[lkA * DD + cA],     h[jt][0]);
            atomicAdd(&g_m[lkA * DD + cA + 1], h[jt][1]);
            atomicAdd(&g_m[lkB * DD + cA],     h[jt][2]);
            atomicAdd(&g_m[lkB * DD + cA + 1], h[jt][3]);
        }
    }

#pragma unroll
    for (int jt = 0; jt < 4; jt++) {
        *(float2*)&g_path_state[pA * DD + 8 * jt + 2 * m] = make_float2(h[jt][0], h[jt][1]);
        *(float2*)&g_path_state[pB * DD + 8 * jt + 2 * m] = make_float2(h[jt][2], h[jt][3]);
    }
}

// ---------------------------------------------------------------------------
// Link phase: warp per link. GRU(m, link_state), then refresh lg, re-zero m.
__global__ void __launch_bounds__(256)
link_kernel(const float* __restrict__ Wl, const float* __restrict__ Ul,
            const float* __restrict__ bl,
            const float* __restrict__ Wp, const float* __restrict__ bp) {
    int w = (blockIdx.x * blockDim.x + threadIdx.x) >> 5;
    int lane = threadIdx.x & 31;
    if (w >= NLK) return;

    float x = g_m[w * DD + lane];
    float h = g_link_state[w * DD + lane];

    float az = __ldg(&bl[lane]),       ar = __ldg(&bl[32 + lane]),  an = __ldg(&bl[64 + lane]);
    float hz = __ldg(&bl[96 + lane]),  hr = __ldg(&bl[128 + lane]), hn = __ldg(&bl[160 + lane]);
#pragma unroll
    for (int l = 0; l < 32; l++) {
        float xl = __shfl_sync(0xffffffffu, x, l);
        float hl = __shfl_sync(0xffffffffu, h, l);
        az = fmaf(xl, __ldg(&Wl[l * 96 + lane]),      az);
        ar = fmaf(xl, __ldg(&Wl[l * 96 + 32 + lane]), ar);
        an = fmaf(xl, __ldg(&Wl[l * 96 + 64 + lane]), an);
        hz = fmaf(hl, __ldg(&Ul[l * 96 + lane]),      hz);
        hr = fmaf(hl, __ldg(&Ul[l * 96 + 32 + lane]), hr);
        hn = fmaf(hl, __ldg(&Ul[l * 96 + 64 + lane]), hn);
    }
    float z = fsig(az + hz);
    float r = fsig(ar + hr);
    float n = ftanhf_(fmaf(r, hn, an));
    float h2 = fmaf(z, h - n, n);
    g_link_state[w * DD + lane] = h2;
    g_m[w * DD + lane] = 0.0f;

    // lg = h2 @ Wp + bp[0]
    float gz = __ldg(&bp[lane]), gr = __ldg(&bp[32 + lane]), gn = __ldg(&bp[64 + lane]);
#pragma unroll
    for (int l = 0; l < 32; l++) {
        float hl = __shfl_sync(0xffffffffu, h2, l);
        gz = fmaf(hl, __ldg(&Wp[l * 96 + lane]),      gz);
        gr = fmaf(hl, __ldg(&Wp[l * 96 + 32 + lane]), gr);
        gn = fmaf(hl, __ldg(&Wp[l * 96 + 64 + lane]), gn);
    }
    g_lg[w * 96 + lane]      = gz;
    g_lg[w * 96 + 32 + lane] = gr;
    g_lg[w * 96 + 64 + lane] = gn;
}

// ---------------------------------------------------------------------------
// Readout: warp handles 4 paths; lane owns 8 contiguous hidden units.
__global__ void __launch_bounds__(256, 2)
readout_kernel(const float* __restrict__ R1, const float* __restrict__ Rb1,
               const float* __restrict__ R2, const float* __restrict__ Rb2,
               const float* __restrict__ R3, const float* __restrict__ Rb3,
               float* __restrict__ out) {
    int w = (blockIdx.x * blockDim.x + threadIdx.x) >> 5;
    int lane = threadIdx.x & 31;
    if (w >= PN / 4) return;
    int p0 = w * 4;
    int cb = lane * 8;

    float ps[4];
#pragma unroll
    for (int q = 0; q < 4; q++) ps[q] = g_path_state[(p0 + q) * DD + lane];

    float4 b1a = __ldg((const float4*)&Rb1[cb]);
    float4 b1b = __ldg((const float4*)&Rb1[cb + 4]);
    float h1[4][8];
#pragma unroll
    for (int q = 0; q < 4; q++) {
        h1[q][0] = b1a.x; h1[q][1] = b1a.y; h1[q][2] = b1a.z; h1[q][3] = b1a.w;
        h1[q][4] = b1b.x; h1[q][5] = b1b.y; h1[q][6] = b1b.z; h1[q][7] = b1b.w;
    }
    for (int l = 0; l < 32; l++) {
        float4 wa = __ldg((const float4*)&R1[l * RUN + cb]);
        float4 wb = __ldg((const float4*)&R1[l * RUN + cb + 4]);
        float wv[8] = {wa.x, wa.y, wa.z, wa.w, wb.x, wb.y, wb.z, wb.w};
#pragma unroll
        for (int q = 0; q < 4; q++) {
            float v = __shfl_sync(0xffffffffu, ps[q], l);
#pragma unroll
            for (int j = 0; j < 8; j++) h1[q][j] = fmaf(v, wv[j], h1[q][j]);
        }
    }
#pragma unroll
    for (int q = 0; q < 4; q++)
#pragma unroll
        for (int j = 0; j < 8; j++) h1[q][j] = fselu(h1[q][j]);

    float4 b2a = __ldg((const float4*)&Rb2[cb]);
    float4 b2b = __ldg((const float4*)&Rb2[cb + 4]);
    float h2[4][8];
#pragma unroll
    for (int q = 0; q < 4; q++) {
        h2[q][0] = b2a.x; h2[q][1] = b2a.y; h2[q][2] = b2a.z; h2[q][3] = b2a.w;
        h2[q][4] = b2b.x; h2[q][5] = b2b.y; h2[q][6] = b2b.z; h2[q][7] = b2b.w;
    }
#pragma unroll
    for (int reg = 0; reg < 8; reg++) {
        for (int owner = 0; owner < 32; owner++) {
            int jj = owner * 8 + reg;
            float4 wa = __ldg((const float4*)&R2[jj * RUN + cb]);
            float4 wb = __ldg((const float4*)&R2[jj * RUN + cb + 4]);
            float wv[8] = {wa.x, wa.y, wa.z, wa.w, wb.x, wb.y, wb.z, wb.w};
#pragma unroll
            for (int q = 0; q < 4; q++) {
                float v = __shfl_sync(0xffffffffu, h1[q][reg], owner);
#pragma unroll
                for (int j = 0; j < 8; j++) h2[q][j] = fmaf(v, wv[j], h2[q][j]);
            }
        }
    }
#pragma unroll
    for (int q = 0; q < 4; q++)
#pragma unroll
        for (int j = 0; j < 8; j++) h2[q][j] = fselu(h2[q][j]);

    float4 r3a = __ldg((const float4*)&R3[cb]);
    float4 r3b = __ldg((const float4*)&R3[cb + 4]);
    float rv[8] = {r3a.x, r3a.y, r3a.z, r3a.w, r3b.x, r3b.y, r3b.z, r3b.w};
    float b3 = __ldg(&Rb3[0]);
#pragma unroll
    for (int q = 0; q < 4; q++) {
        float o = 0.0f;
#pragma unroll
        for (int j = 0; j < 8; j++) o = fmaf(h2[q][j], rv[j], o);
#pragma unroll
        for (int off = 16; off > 0; off >>= 1) o += __shfl_xor_sync(0xffffffffu, o, off);
        if (lane == 0) out[p0 + q] = o + b3;
    }
}

// ---------------------------------------------------------------------------
extern "C" void kernel_launch(void* const* d_in, const int* in_sizes, int n_in,
                              void* d_out, int out_size) {
    const int*   links = (const int*)d_in[0];
    const float* cap = (const float*)d_in[3];
    const float* pol = (const float*)d_in[4];
    const float* wt  = (const float*)d_in[5];
    const float* bw  = (const float*)d_in[6];
    const float* tos = (const float*)d_in[7];
    const float* pk  = (const float*)d_in[8];
    const float* avg = (const float*)d_in[9];
    const float* Wp  = (const float*)d_in[10];
    const float* Up  = (const float*)d_in[11];
    const float* bp  = (const float*)d_in[12];
    const float* Wl  = (const float*)d_in[13];
    const float* Ul  = (const float*)d_in[14];
    const float* bl  = (const float*)d_in[15];
    const float* R1  = (const float*)d_in[16];
    const float* Rb1 = (const float*)d_in[17];
    const float* R2  = (const float*)d_in[18];
    const float* Rb2 = (const float*)d_in[19];
    const float* R3  = (const float*)d_in[20];
    const float* Rb3 = (const float*)d_in[21];
    float* out = (float*)d_out;

    init_path_kernel<<<(PN * DD + 255) / 256, 256>>>(bw, tos, pk, avg);
    init_link_kernel<<<(NLK * 32 + 255) / 256, 256>>>(cap, pol, wt, Wp, bp);

    int nwarps = (PN + 15) / 16;               // 6250
    int pblocks = (nwarps + 3) / 4;            // 128 threads = 4 warps per block
    for (int t = 0; t < TT; t++) {
        path_mma_kernel<<<pblocks, 128>>>(links, Up, bp);
        if (t < TT - 1)  // final link update is dead (readout uses path_state only)
            link_kernel<<<(NLK * 32 + 255) / 256, 256>>>(Wl, Ul, bl, Wp, bp);
    }

    readout_kernel<<<((PN / 4) * 32 + 255) / 256, 256>>>(R1, Rb1, R2, Rb2, R3, Rb3, out);
}

// round 5
// speedup vs baseline: 1.4903x; 1.1704x over previous
#include <cuda_runtime.h>
#include <cstdint>

#define PN 100000
#define LLEN 5
#define NLK 10000
#define DD 32
#define TT 8
#define RUN 256

// Scratch (no allocations allowed)
__device__ float g_path_state[PN * DD];        // 12.8 MB
__device__ float g_link_state[NLK * DD];       // 1.28 MB
__device__ float g_lg[NLK * 3 * DD];           // 3.84 MB
__device__ float g_m[NLK * DD];                // 1.28 MB
__device__ float g_h1[PN * RUN];               // 102.4 MB : readout hidden 1

__device__ __forceinline__ float fexp2(float x) {
    float r; asm("ex2.approx.f32 %0, %1;" : "=f"(r) : "f"(x)); return r;
}
__device__ __forceinline__ float frcp(float x) {
    float r; asm("rcp.approx.f32 %0, %1;" : "=f"(r) : "f"(x)); return r;
}
__device__ __forceinline__ float fsig(float x) {
    return frcp(1.0f + fexp2(-1.4426950408889634f * x));
}
__device__ __forceinline__ float ftanhf_(float x) {
    float e = fexp2(-2.8853900817779268f * x);
    return fmaf(2.0f, frcp(1.0f + e), -1.0f);
}
__device__ __forceinline__ float fselu(float x) {
    const float sc = 1.0507009873554805f;
    const float sa = 1.7580993408473768f;
    float neg = sa * (fexp2(1.4426950408889634f * x) - 1.0f);
    return x > 0.0f ? sc * x : neg;
}
__device__ __forceinline__ unsigned cvt_tf32(float f) {
    unsigned u; asm("cvt.rna.tf32.f32 %0, %1;" : "=r"(u) : "f"(f)); return u;
}
__device__ __forceinline__ void mma_tf32(float d[4], const unsigned a[4], const unsigned b0,
                                         const unsigned b1) {
    asm volatile(
        "mma.sync.aligned.m16n8k8.row.col.f32.tf32.tf32.f32 "
        "{%0,%1,%2,%3},{%4,%5,%6,%7},{%8,%9},{%0,%1,%2,%3};"
        : "+f"(d[0]), "+f"(d[1]), "+f"(d[2]), "+f"(d[3])
        : "r"(a[0]), "r"(a[1]), "r"(a[2]), "r"(a[3]), "r"(b0), "r"(b1));
}
// Split a float into tf32 hi + tf32 lo
__device__ __forceinline__ void tf32_split(float v, unsigned& hi, unsigned& lo) {
    hi = cvt_tf32(v);
    lo = cvt_tf32(v - __uint_as_float(hi));
}

// ---------------------------------------------------------------------------
__global__ void init_path_kernel(const float* __restrict__ bw, const float* __restrict__ tos,
                                 const float* __restrict__ pk, const float* __restrict__ avg) {
    int i = blockIdx.x * blockDim.x + threadIdx.x;
    if (i >= PN * DD) return;
    int p = i >> 5, c = i & 31;
    float v = 0.0f;
    if (c == 0) v = bw[p];
    else if (c == 1) v = tos[p];
    else if (c == 2) v = pk[p];
    else if (c == 3) v = avg[p];
    g_path_state[i] = v;
}

__global__ void init_link_kernel(const float* __restrict__ cap, const float* __restrict__ pol,
                                 const float* __restrict__ wt,
                                 const float* __restrict__ Wp, const float* __restrict__ bp) {
    int w = (blockIdx.x * blockDim.x + threadIdx.x) >> 5;
    int lane = threadIdx.x & 31;
    if (w >= NLK) return;
    float c0 = __ldg(&cap[w]), c1 = __ldg(&pol[w]), c2 = __ldg(&wt[w]);
    float v = (lane == 0) ? c0 : (lane == 1) ? c1 : (lane == 2) ? c2 : 0.0f;
    g_link_state[w * DD + lane] = v;
    g_m[w * DD + lane] = 0.0f;
#pragma unroll
    for (int g = 0; g < 3; g++) {
        int c = g * 32 + lane;
        float o = __ldg(&bp[c]);
        o = fmaf(c0, __ldg(&Wp[c]),       o);
        o = fmaf(c1, __ldg(&Wp[96 + c]),  o);
        o = fmaf(c2, __ldg(&Wp[192 + c]), o);
        g_lg[w * 96 + c] = o;
    }
}

// ---------------------------------------------------------------------------
// Path phase via tensor cores with 3xTF32 error compensation (unchanged, R4-proven).
__global__ void __launch_bounds__(128)
path_mma_kernel(const int* __restrict__ links, const float* __restrict__ Up,
                const float* __restrict__ bp) {
    __shared__ uint4 sB[48 * 32];   // [(nt*4+kt)*32 + lane] = {hi0, hi1, lo0, lo1}

    int lane = threadIdx.x & 31;

    for (int idx = threadIdx.x; idx < 48 * 32; idx += blockDim.x) {
        int li = idx & 31;
        int t = idx >> 5;
        int nt = t >> 2, kt = t & 3;
        int gi = li >> 2, mi = li & 3;
        float w0 = __ldg(&Up[(kt * 8 + mi)     * 96 + nt * 8 + gi]);
        float w1 = __ldg(&Up[(kt * 8 + mi + 4) * 96 + nt * 8 + gi]);
        unsigned h0 = cvt_tf32(w0), h1 = cvt_tf32(w1);
        unsigned l0 = cvt_tf32(w0 - __uint_as_float(h0));
        unsigned l1 = cvt_tf32(w1 - __uint_as_float(h1));
        sB[idx] = make_uint4(h0, h1, l0, l1);
    }
    __syncthreads();

    int wid = (blockIdx.x * blockDim.x + threadIdx.x) >> 5;
    int p0 = wid * 16;
    if (p0 >= PN) return;
    int g = lane >> 2, m = lane & 3;
    int pA = p0 + g, pB = p0 + g + 8;

    float h[4][4];
#pragma unroll
    for (int jt = 0; jt < 4; jt++) {
        float2 ha = *(const float2*)&g_path_state[pA * DD + 8 * jt + 2 * m];
        float2 hb = *(const float2*)&g_path_state[pB * DD + 8 * jt + 2 * m];
        h[jt][0] = ha.x; h[jt][1] = ha.y; h[jt][2] = hb.x; h[jt][3] = hb.y;
    }

    int src0 = (lane & ~3) | (m >> 1);
    int src1 = src0 + 2;
    bool odd = (m & 1);

#pragma unroll 1
    for (int s = 0; s < LLEN; s++) {
        int lkA = __ldg(&links[pA * LLEN + s]);
        int lkB = __ldg(&links[pB * LLEN + s]);
        const float* lgA = g_lg + lkA * 96;
        const float* lgB = g_lg + lkB * 96;

        unsigned ah[4][4], al[4][4];
#pragma unroll
        for (int kt = 0; kt < 4; kt++) {
            float v[4];
            float s00 = __shfl_sync(0xffffffffu, h[kt][0], src0);
            float s01 = __shfl_sync(0xffffffffu, h[kt][1], src0);
            v[0] = odd ? s01 : s00;
            float s10 = __shfl_sync(0xffffffffu, h[kt][2], src0);
            float s11 = __shfl_sync(0xffffffffu, h[kt][3], src0);
            v[1] = odd ? s11 : s10;
            float s20 = __shfl_sync(0xffffffffu, h[kt][0], src1);
            float s21 = __shfl_sync(0xffffffffu, h[kt][1], src1);
            v[2] = odd ? s21 : s20;
            float s30 = __shfl_sync(0xffffffffu, h[kt][2], src1);
            float s31 = __shfl_sync(0xffffffffu, h[kt][3], src1);
            v[3] = odd ? s31 : s30;
#pragma unroll
            for (int e = 0; e < 4; e++) tf32_split(v[e], ah[kt][e], al[kt][e]);
        }

        float d[12][4];
#pragma unroll
        for (int nt = 0; nt < 8; nt++) {
            int gate = nt >> 2, jt = nt & 3;
            int coff = gate * 32 + 8 * jt + 2 * m;
            float2 br = *(const float2*)&bp[96 + coff];
            float2 xA = *(const float2*)&lgA[coff];
            float2 xB = *(const float2*)&lgB[coff];
            d[nt][0] = xA.x + br.x; d[nt][1] = xA.y + br.y;
            d[nt][2] = xB.x + br.x; d[nt][3] = xB.y + br.y;
        }
#pragma unroll
        for (int nt = 8; nt < 12; nt++) {
            int jt = nt & 3;
            int coff = 64 + 8 * jt + 2 * m;
            float2 br = *(const float2*)&bp[96 + coff];
            d[nt][0] = br.x; d[nt][1] = br.y; d[nt][2] = br.x; d[nt][3] = br.y;
        }

#pragma unroll
        for (int nt = 0; nt < 12; nt++)
#pragma unroll
            for (int kt = 0; kt < 4; kt++) {
                uint4 b = sB[(nt * 4 + kt) * 32 + lane];
                mma_tf32(d[nt], ah[kt], b.x, b.y);
                mma_tf32(d[nt], al[kt], b.x, b.y);
                mma_tf32(d[nt], ah[kt], b.z, b.w);
            }

#pragma unroll
        for (int jt = 0; jt < 4; jt++) {
            int coff = 64 + 8 * jt + 2 * m;
            float2 xnA = *(const float2*)&lgA[coff];
            float2 xnB = *(const float2*)&lgB[coff];
            float xn[4] = {xnA.x, xnA.y, xnB.x, xnB.y};
#pragma unroll
            for (int e = 0; e < 4; e++) {
                float z = fsig(d[jt][e]);
                float r = fsig(d[4 + jt][e]);
                float n = ftanhf_(fmaf(r, d[8 + jt][e], xn[e]));
                h[jt][e] = fmaf(z, h[jt][e] - n, n);
            }
            int cA = 8 * jt + 2 * m;
            atomicAdd(&g_m[lkA * DD + cA],     h[jt][0]);
            atomicAdd(&g_m[lkA * DD + cA + 1], h[jt][1]);
            atomicAdd(&g_m[lkB * DD + cA],     h[jt][2]);
            atomicAdd(&g_m[lkB * DD + cA + 1], h[jt][3]);
        }
    }

#pragma unroll
    for (int jt = 0; jt < 4; jt++) {
        *(float2*)&g_path_state[pA * DD + 8 * jt + 2 * m] = make_float2(h[jt][0], h[jt][1]);
        *(float2*)&g_path_state[pB * DD + 8 * jt + 2 * m] = make_float2(h[jt][2], h[jt][3]);
    }
}

// ---------------------------------------------------------------------------
__global__ void __launch_bounds__(256)
link_kernel(const float* __restrict__ Wl, const float* __restrict__ Ul,
            const float* __restrict__ bl,
            const float* __restrict__ Wp, const float* __restrict__ bp) {
    int w = (blockIdx.x * blockDim.x + threadIdx.x) >> 5;
    int lane = threadIdx.x & 31;
    if (w >= NLK) return;

    float x = g_m[w * DD + lane];
    float h = g_link_state[w * DD + lane];

    float az = __ldg(&bl[lane]),       ar = __ldg(&bl[32 + lane]),  an = __ldg(&bl[64 + lane]);
    float hz = __ldg(&bl[96 + lane]),  hr = __ldg(&bl[128 + lane]), hn = __ldg(&bl[160 + lane]);
#pragma unroll
    for (int l = 0; l < 32; l++) {
        float xl = __shfl_sync(0xffffffffu, x, l);
        float hl = __shfl_sync(0xffffffffu, h, l);
        az = fmaf(xl, __ldg(&Wl[l * 96 + lane]),      az);
        ar = fmaf(xl, __ldg(&Wl[l * 96 + 32 + lane]), ar);
        an = fmaf(xl, __ldg(&Wl[l * 96 + 64 + lane]), an);
        hz = fmaf(hl, __ldg(&Ul[l * 96 + lane]),      hz);
        hr = fmaf(hl, __ldg(&Ul[l * 96 + 32 + lane]), hr);
        hn = fmaf(hl, __ldg(&Ul[l * 96 + 64 + lane]), hn);
    }
    float z = fsig(az + hz);
    float r = fsig(ar + hr);
    float n = ftanhf_(fmaf(r, hn, an));
    float h2 = fmaf(z, h - n, n);
    g_link_state[w * DD + lane] = h2;
    g_m[w * DD + lane] = 0.0f;

    float gz = __ldg(&bp[lane]), gr = __ldg(&bp[32 + lane]), gn = __ldg(&bp[64 + lane]);
#pragma unroll
    for (int l = 0; l < 32; l++) {
        float hl = __shfl_sync(0xffffffffu, h2, l);
        gz = fmaf(hl, __ldg(&Wp[l * 96 + lane]),      gz);
        gr = fmaf(hl, __ldg(&Wp[l * 96 + 32 + lane]), gr);
        gn = fmaf(hl, __ldg(&Wp[l * 96 + 64 + lane]), gn);
    }
    g_lg[w * 96 + lane]      = gz;
    g_lg[w * 96 + 32 + lane] = gr;
    g_lg[w * 96 + 64 + lane] = gn;
}

// ---------------------------------------------------------------------------
// Readout layer 1 (mma 3xTF32): H1 = selu(PS[16,32] @ R1[32,256] + b1) -> g_h1.
// Warp = 16 paths; R1 staged in fragment order (float2) in 32KB smem.
__global__ void __launch_bounds__(256)
readout1_kernel(const float* __restrict__ R1, const float* __restrict__ Rb1) {
    __shared__ float2 sB[32 * 4 * 32];   // [(nt*4+kt)*32 + lane] = {b0, b1}

    int lane = threadIdx.x & 31;
    for (int idx = threadIdx.x; idx < 32 * 4 * 32; idx += blockDim.x) {
        int li = idx & 31;
        int t = idx >> 5;             // nt*4 + kt
        int nt = t >> 2, kt = t & 3;
        int gi = li >> 2, mi = li & 3;
        sB[idx] = make_float2(__ldg(&R1[(kt * 8 + mi)     * RUN + nt * 8 + gi]),
                              __ldg(&R1[(kt * 8 + mi + 4) * RUN + nt * 8 + gi]));
    }
    __syncthreads();

    int wid = (blockIdx.x * blockDim.x + threadIdx.x) >> 5;
    int p0 = wid * 16;
    if (p0 >= PN) return;
    int g = lane >> 2, m = lane & 3;
    int pA = p0 + g, pB = p0 + g + 8;

    // A fragments from path_state (row-major): a0=A[g][k], a1=A[g+8][k], k = kt*8 + m / m+4
    unsigned ah[4][4], al[4][4];
#pragma unroll
    for (int kt = 0; kt < 4; kt++) {
        tf32_split(__ldg(&g_path_state[pA * DD + kt * 8 + m]),     ah[kt][0], al[kt][0]);
        tf32_split(__ldg(&g_path_state[pB * DD + kt * 8 + m]),     ah[kt][1], al[kt][1]);
        tf32_split(__ldg(&g_path_state[pA * DD + kt * 8 + m + 4]), ah[kt][2], al[kt][2]);
        tf32_split(__ldg(&g_path_state[pB * DD + kt * 8 + m + 4]), ah[kt][3], al[kt][3]);
    }

#pragma unroll 1
    for (int half = 0; half < 2; half++) {
        float d[16][4];
#pragma unroll
        for (int ntl = 0; ntl < 16; ntl++) {
            int col = (half * 16 + ntl) * 8 + 2 * m;
            float2 b = *(const float2*)&Rb1[col];
            d[ntl][0] = b.x; d[ntl][1] = b.y; d[ntl][2] = b.x; d[ntl][3] = b.y;
        }
#pragma unroll
        for (int ntl = 0; ntl < 16; ntl++) {
            int nt = half * 16 + ntl;
#pragma unroll
            for (int kt = 0; kt < 4; kt++) {
                float2 b = sB[(nt * 4 + kt) * 32 + lane];
                unsigned bh0, bl0, bh1, bl1;
                tf32_split(b.x, bh0, bl0);
                tf32_split(b.y, bh1, bl1);
                mma_tf32(d[ntl], ah[kt], bh0, bh1);
                mma_tf32(d[ntl], al[kt], bh0, bh1);
                mma_tf32(d[ntl], ah[kt], bl0, bl1);
            }
        }
#pragma unroll
        for (int ntl = 0; ntl < 16; ntl++) {
            int col = (half * 16 + ntl) * 8 + 2 * m;
            *(float2*)&g_h1[pA * RUN + col] = make_float2(fselu(d[ntl][0]), fselu(d[ntl][1]));
            *(float2*)&g_h1[pB * RUN + col] = make_float2(fselu(d[ntl][2]), fselu(d[ntl][3]));
        }
    }
}

// ---------------------------------------------------------------------------
// Readout layers 2+3 (mma 3xTF32): out = selu(H1 @ R2 + b2) @ R3 + b3.
// Warp = 16 paths. R2 staged per (half, kc) chunk: 16 nt x 8 kt fragments in
// 32KB smem, hi/lo split at use (rides the idle fma/alu pipes).
__global__ void __launch_bounds__(256)
readout2_kernel(const float* __restrict__ R2, const float* __restrict__ Rb2,
                const float* __restrict__ R3, const float* __restrict__ Rb3,
                float* __restrict__ out) {
    __shared__ float2 sB[16 * 8 * 32];   // [(ntl*8+kt)*32 + lane]

    int lane = threadIdx.x & 31;
    int wid = (blockIdx.x * blockDim.x + threadIdx.x) >> 5;
    int p0 = wid * 16;
    bool active = (p0 < PN);
    int g = lane >> 2, m = lane & 3;
    int pA = p0 + g, pB = p0 + g + 8;

    float accA = 0.0f, accB = 0.0f;

#pragma unroll 1
    for (int half = 0; half < 2; half++) {
        float d[16][4];
        if (active) {
#pragma unroll
            for (int ntl = 0; ntl < 16; ntl++) {
                int col = half * 128 + ntl * 8 + 2 * m;
                float2 b = *(const float2*)&Rb2[col];
                d[ntl][0] = b.x; d[ntl][1] = b.y; d[ntl][2] = b.x; d[ntl][3] = b.y;
            }
        }
#pragma unroll 1
        for (int kc = 0; kc < 4; kc++) {
            __syncthreads();
            // stage B fragments for this (half, kc) chunk
            for (int idx = threadIdx.x; idx < 16 * 8 * 32; idx += blockDim.x) {
                int li = idx & 31;
                int t = idx >> 5;           // ntl*8 + kt
                int ntl = t >> 3, kt = t & 7;
                int gi = li >> 2, mi = li & 3;
                int krow = kc * 64 + kt * 8;
                int col = half * 128 + ntl * 8 + gi;
                sB[idx] = make_float2(__ldg(&R2[(krow + mi)     * RUN + col]),
                                      __ldg(&R2[(krow + mi + 4) * RUN + col]));
            }
            __syncthreads();
            if (!active) continue;

            // A fragments for this k-chunk from g_h1
            unsigned ah[8][4], al[8][4];
#pragma unroll
            for (int kt = 0; kt < 8; kt++) {
                int k0 = kc * 64 + kt * 8;
                tf32_split(__ldg(&g_h1[pA * RUN + k0 + m]),     ah[kt][0], al[kt][0]);
                tf32_split(__ldg(&g_h1[pB * RUN + k0 + m]),     ah[kt][1], al[kt][1]);
                tf32_split(__ldg(&g_h1[pA * RUN + k0 + m + 4]), ah[kt][2], al[kt][2]);
                tf32_split(__ldg(&g_h1[pB * RUN + k0 + m + 4]), ah[kt][3], al[kt][3]);
            }
#pragma unroll
            for (int ntl = 0; ntl < 16; ntl++)
#pragma unroll
                for (int kt = 0; kt < 8; kt++) {
                    float2 b = sB[(ntl * 8 + kt) * 32 + lane];
                    unsigned bh0, bl0, bh1, bl1;
                    tf32_split(b.x, bh0, bl0);
                    tf32_split(b.y, bh1, bl1);
                    mma_tf32(d[ntl], ah[kt], bh0, bh1);
                    mma_tf32(d[ntl], al[kt], bh0, bh1);
                    mma_tf32(d[ntl], ah[kt], bl0, bl1);
                }
        }
        if (active) {
            // selu + layer-3 partial dot
#pragma unroll
            for (int ntl = 0; ntl < 16; ntl++) {
                int col = half * 128 + ntl * 8 + 2 * m;
                float2 r3 = *(const float2*)&R3[col];
                accA = fmaf(fselu(d[ntl][0]), r3.x, accA);
                accA = fmaf(fselu(d[ntl][1]), r3.y, accA);
                accB = fmaf(fselu(d[ntl][2]), r3.x, accB);
                accB = fmaf(fselu(d[ntl][3]), r3.y, accB);
            }
        }
    }

    if (active) {
        // reduce over the 4 lanes of each quad (m = 0..3)
        accA += __shfl_xor_sync(0xffffffffu, accA, 1);
        accA += __shfl_xor_sync(0xffffffffu, accA, 2);
        accB += __shfl_xor_sync(0xffffffffu, accB, 1);
        accB += __shfl_xor_sync(0xffffffffu, accB, 2);
        if (m == 0) {
            float b3 = __ldg(&Rb3[0]);
            out[pA] = accA + b3;
            out[pB] = accB + b3;
        }
    }
}

// ---------------------------------------------------------------------------
extern "C" void kernel_launch(void* const* d_in, const int* in_sizes, int n_in,
                              void* d_out, int out_size) {
    const int*   links = (const int*)d_in[0];
    const float* cap = (const float*)d_in[3];
    const float* pol = (const float*)d_in[4];
    const float* wt  = (const float*)d_in[5];
    const float* bw  = (const float*)d_in[6];
    const float* tos = (const float*)d_in[7];
    const float* pk  = (const float*)d_in[8];
    const float* avg = (const float*)d_in[9];
    const float* Wp  = (const float*)d_in[10];
    const float* Up  = (const float*)d_in[11];
    const float* bp  = (const float*)d_in[12];
    const float* Wl  = (const float*)d_in[13];
    const float* Ul  = (const float*)d_in[14];
    const float* bl  = (const float*)d_in[15];
    const float* R1  = (const float*)d_in[16];
    const float* Rb1 = (const float*)d_in[17];
    const float* R2  = (const float*)d_in[18];
    const float* Rb2 = (const float*)d_in[19];
    const float* R3  = (const float*)d_in[20];
    const float* Rb3 = (const float*)d_in[21];
    float* out = (float*)d_out;

    init_path_kernel<<<(PN * DD + 255) / 256, 256>>>(bw, tos, pk, avg);
    init_link_kernel<<<(NLK * 32 + 255) / 256, 256>>>(cap, pol, wt, Wp, bp);

    int nwarps = (PN + 15) / 16;               // 6250
    int pblocks = (nwarps + 3) / 4;            // 128 threads = 4 warps per block
    for (int t = 0; t < TT; t++) {
        path_mma_kernel<<<pblocks, 128>>>(links, Up, bp);
        if (t < TT - 1)
            link_kernel<<<(NLK * 32 + 255) / 256, 256>>>(Wl, Ul, bl, Wp, bp);
    }

    int rblocks = (nwarps + 7) / 8;            // 256 threads = 8 warps per block
    readout1_kernel<<<rblocks, 256>>>(R1, Rb1);
    readout2_kernel<<<rblocks, 256>>>(R2, Rb2, R3, Rb3, out);
}